// round 17
// baseline (speedup 1.0000x reference)
#include <cuda_runtime.h>
#include <math.h>
#include <stdint.h>

#define BATCH 4
#define SEQ   1024
#define HID   768
#define HEADS 12
#define NENT  32
#define MENT  4
#define WD    768
#define AD    256
#define NC    97
#define NCP   128          // padded classifier width
#define SPLITK 64
#define DD    12
#define PP    144          // DD*DD
#define PP2   160          // K-padded (zeros) for BK=32 GEMM
#define NPAIR (NENT*NENT)  // 1024

// ---------------- device scratch ----------------
__device__ float d_rep[BATCH*NENT*HID];
__device__ float d_rso[BATCH*NENT*2*WD];
__device__ float d_Wso[WD*2*WD];
__device__ float d_seqR[(size_t)BATCH*SEQ*HID];   // tf32-rounded seq
__device__ float d_WcR[HID*WD];
__device__ float d_WaR[WD*AD];
__device__ float d_clfR[WD*NCP];                  // rounded + padded clf_W
__device__ float d_seqWc[(size_t)BATCH*SEQ*WD];   // rnd(seq @ W_c), tf32-rounded
__device__ float d_ga [BATCH*NENT*HEADS*SEQ];
__device__ float d_pa [(size_t)BATCH*NPAIR*SEQ];  // unnormalized, tf32-rounded
__device__ float d_painv[BATCH*NPAIR];
__device__ float d_Zs [(size_t)BATCH*NPAIR*WD];
__device__ float d_Zo [(size_t)BATCH*NPAIR*WD];
__device__ float d_P  [(size_t)BATCH*NPAIR*PP2];  // cols 144..159 stay zero
__device__ float d_g  [(size_t)BATCH*NPAIR*WD];
__device__ float d_e  [BATCH*NPAIR];
__device__ float d_Ablt[PP2*WD];                  // rows 144..159 stay zero
__device__ float d_gclf[(size_t)BATCH*NPAIR*NCP];
__device__ float d_rgcg[2*BATCH*NENT*NC];
__device__ float d_part [3300000];                // rso / t split-K partials
__device__ float d_part2[3300000];                // gclf split-K partials (concurrent)

// ---------------- helpers ----------------
__device__ __forceinline__ uint32_t f2tf32(float x)
{
    uint32_t r;
    asm("cvt.rna.tf32.f32 %0, %1;" : "=r"(r) : "f"(x));
    return r;
}
__device__ __forceinline__ float rnd32(float x) { return __uint_as_float(f2tf32(x)); }

__device__ __forceinline__ void mma_tf32(float* c, const uint32_t* a, const uint32_t* b)
{
    asm volatile(
        "mma.sync.aligned.m16n8k8.row.col.f32.tf32.tf32.f32 "
        "{%0,%1,%2,%3}, {%4,%5,%6,%7}, {%8,%9}, {%0,%1,%2,%3};"
        : "+f"(c[0]), "+f"(c[1]), "+f"(c[2]), "+f"(c[3])
        : "r"(a[0]), "r"(a[1]), "r"(a[2]), "r"(a[3]), "r"(b[0]), "r"(b[1]));
}

__device__ __forceinline__ void cp16(uint32_t smem, const void* g)
{
    asm volatile("cp.async.cg.shared.global [%0], [%1], 16;" :: "r"(smem), "l"(g));
}
__device__ __forceinline__ uint32_t smem_u32(const void* p)
{
    return (uint32_t)__cvta_generic_to_shared(p);
}

// ---------------- BK=32 cp.async pipelined tf32 GEMM ----------------
// C[M,N] = A[M,K] row * B[K,N] row, operands pre-rounded to tf32.
// BM=128, BN=64, BK=32. 8 warps: 4 m x 2 n, warp tile 32x32.
// As[128][36] / Bs[32][72]: conflict-free cp.async stores AND fragment LDS.
// 2-stage ring, wait_group 0; 32 HMMA/warp between barriers. 3 blocks/SM.
// MODE 0: C = acc (+ biasScale*bias[n]).
// MODE 1: C = tanh(acc + bias[(gm>>5)*bS+gn]); C2 likewise with bias2.
// MODE 2: C = acc * bias[zb*bS+gm].
// MODE 3: v = acc * scale[zb*NPAIR+gm];
//         C  = tanh(v + bias [((zb*NENT)+(gm>>5))*bS+gn]);
//         C2 = tanh(v + bias2[...same row...]).
// RND: round stored C to tf32 (MODE 0/2).
// Requirements: M%128==0, (K/kSplit)%32==0, N%4==0.
#define AS_STRIDE 36
#define BS_STRIDE 72
template<int MODE, int RND>
__global__ __launch_bounds__(256, 3)
void mma_gemm(const float* __restrict__ A, const float* __restrict__ B,
              float* __restrict__ C, float* __restrict__ C2,
              int M, int N, int K,
              long long sA, long long sB, long long sC,
              int kSplit, long long partStride,
              const float* __restrict__ bias, float biasScale,
              const float* __restrict__ bias2, int biasStride,
              const float* __restrict__ scale)
{
    const int NWT = 4;
    const int BN  = 64;
    __shared__ uint32_t As[2][128 * AS_STRIDE];   // 2 x 18 KB
    __shared__ float    Bs[2][32 * BS_STRIDE];    // 2 x 9 KB

    int zb = blockIdx.z / kSplit;
    int kz = blockIdx.z - zb * kSplit;
    A += (long long)zb * sA;
    B += (long long)zb * sB;
    C += (long long)zb * sC + (long long)kz * partStride;
    if (C2) C2 += (long long)zb * sC;             // batch-offset second output

    int row0 = blockIdx.y * 128;
    int col0 = blockIdx.x * BN;
    int tid = threadIdx.x, lane = tid & 31, w = tid >> 5;
    int wm = w & 3, wn = w >> 2;
    int g = lane >> 2, t = lane & 3;

    int kLen = K / kSplit;
    int k0beg = kz * kLen, k0end = k0beg + kLen;

    float acc[2][NWT][4];
    #pragma unroll
    for (int i = 0; i < 2; i++)
        #pragma unroll
        for (int j = 0; j < NWT; j++)
            #pragma unroll
            for (int r = 0; r < 4; r++) acc[i][j][r] = 0.f;

    int am = tid >> 3, ak = (tid & 7) * 4;
    const float* gA = A + (long long)(row0 + am) * K + ak;
    uint32_t asA = smem_u32(&As[0][am * AS_STRIDE + ak]);
    const uint32_t strideAstg = 128 * AS_STRIDE * 4;
    const uint32_t strideArow = 32 * AS_STRIDE * 4;

    int bk = tid >> 4, bn = (tid & 15) * 4;
    uint32_t bsB = smem_u32(&Bs[0][bk * BS_STRIDE + bn]);
    const uint32_t strideBstg = 32 * BS_STRIDE * 4;
    const uint32_t strideBrow = 16 * BS_STRIDE * 4;

    // prologue
    {
        #pragma unroll
        for (int p = 0; p < 4; p++)
            cp16(asA + p * strideArow, gA + (long long)p * 32 * K + k0beg);
        #pragma unroll
        for (int p = 0; p < 2; p++)
            cp16(bsB + p * strideBrow,
                 B + (long long)(k0beg + bk + p * 16) * N + col0 + bn);
        asm volatile("cp.async.commit_group;");
    }

    int buf = 0;
    for (int k0 = k0beg; k0 < k0end; k0 += 32) {
        asm volatile("cp.async.wait_group 0;");
        __syncthreads();

        int kn = k0 + 32;
        if (kn < k0end) {
            uint32_t ao = (buf ^ 1) ? strideAstg : 0;
            uint32_t bo = (buf ^ 1) ? strideBstg : 0;
            #pragma unroll
            for (int p = 0; p < 4; p++)
                cp16(asA + ao + p * strideArow, gA + (long long)p * 32 * K + kn);
            #pragma unroll
            for (int p = 0; p < 2; p++)
                cp16(bsB + bo + p * strideBrow,
                     B + (long long)(kn + bk + p * 16) * N + col0 + bn);
            asm volatile("cp.async.commit_group;");
        }

        const uint32_t* as = As[buf];
        const float*    bs = Bs[buf];
        #pragma unroll
        for (int k8 = 0; k8 < 4; k8++) {
            int kb = k8 * 8;
            uint32_t a[2][4];
            #pragma unroll
            for (int mi = 0; mi < 2; mi++) {
                int mb = wm * 32 + mi * 16;
                a[mi][0] = as[(mb + g)     * AS_STRIDE + kb + t];
                a[mi][1] = as[(mb + g + 8) * AS_STRIDE + kb + t];
                a[mi][2] = as[(mb + g)     * AS_STRIDE + kb + t + 4];
                a[mi][3] = as[(mb + g + 8) * AS_STRIDE + kb + t + 4];
            }
            uint32_t b[NWT][2];
            #pragma unroll
            for (int ni = 0; ni < NWT; ni++) {
                int nb_ = wn * 32 + ni * 8 + g;
                b[ni][0] = __float_as_uint(bs[(kb + t)     * BS_STRIDE + nb_]);
                b[ni][1] = __float_as_uint(bs[(kb + t + 4) * BS_STRIDE + nb_]);
            }
            #pragma unroll
            for (int mi = 0; mi < 2; mi++)
                #pragma unroll
                for (int ni = 0; ni < NWT; ni++)
                    mma_tf32(acc[mi][ni], a[mi], b[ni]);
        }
        buf ^= 1;
    }

    // ---- epilogue ----
    #pragma unroll
    for (int mi = 0; mi < 2; mi++) {
        #pragma unroll
        for (int ni = 0; ni < NWT; ni++) {
            int m_base = row0 + wm * 32 + mi * 16 + g;
            int n_base = col0 + wn * 32 + ni * 8 + t * 2;
            #pragma unroll
            for (int r = 0; r < 4; r++) {
                int gm = m_base + ((r >> 1) << 3);
                int gn = n_base + (r & 1);
                if (gn >= N) continue;
                float v = acc[mi][ni][r];
                if (MODE == 0) {
                    if (bias) v += biasScale * bias[gn];
                    if (RND) v = rnd32(v);
                    C[(long long)gm * N + gn] = v;
                } else if (MODE == 1) {
                    long long br = (long long)(gm >> 5) * biasStride + gn;
                    C [(long long)gm * N + gn] = tanhf(v + bias [br]);
                    C2[(long long)gm * N + gn] = tanhf(v + bias2[br]);
                } else if (MODE == 2) {
                    v *= bias[(long long)zb * biasStride + gm];
                    if (RND) v = rnd32(v);
                    C[(long long)gm * N + gn] = v;
                } else {
                    float vv = v * scale[(long long)zb * NPAIR + gm];
                    long long br = (long long)((zb << 5) + (gm >> 5)) * biasStride + gn;
                    C [(long long)gm * N + gn] = tanhf(vv + bias [br]);
                    C2[(long long)gm * N + gn] = tanhf(vv + bias2[br]);
                }
            }
        }
    }
}

__global__ void reduce_add_kernel(const float* __restrict__ src, float* __restrict__ dst,
                                  int parts, long long len)
{
    long long i = (long long)blockIdx.x * 256 + threadIdx.x;
    if (i >= len) return;
    float s = 0.f;
    for (int p = 0; p < parts; p++) s += src[(long long)p * len + i];
    dst[i] = s;
}

// ---------------- stage kernels ----------------
__global__ void rep_kernel(const float* __restrict__ seq, const int* __restrict__ ep)
{
    int bn = blockIdx.x;
    int b = bn / NENT, n = bn % NENT;
    int e0 = ep[(b * NENT + n) * MENT + 0];
    int e1 = ep[(b * NENT + n) * MENT + 1];
    int e2 = ep[(b * NENT + n) * MENT + 2];
    int e3 = ep[(b * NENT + n) * MENT + 3];
    const float* sb = seq + (long long)b * SEQ * HID;
    for (int h = threadIdx.x; h < HID; h += blockDim.x) {
        float v0 = sb[(long long)e0 * HID + h];
        float v1 = sb[(long long)e1 * HID + h];
        float v2 = sb[(long long)e2 * HID + h];
        float v3 = sb[(long long)e3 * HID + h];
        float m = fmaxf(fmaxf(v0, v1), fmaxf(v2, v3));
        float s = expf(v0 - m) + expf(v1 - m) + expf(v2 - m) + expf(v3 - m);
        d_rep[(b * NENT + n) * HID + h] = rnd32(m + logf(s));
    }
}

// side1 prep: round seq and W_c (operands of the seqWc GEMM)
__global__ void prep_seqWc_kernel(const float* __restrict__ seq,
                                  const float* __restrict__ Wc)
{
    const long long n1 = (long long)BATCH * SEQ * HID;
    const long long n2 = (long long)HID * WD;
    long long idx = (long long)blockIdx.x * 256 + threadIdx.x;
    if (idx < n1) { d_seqR[idx] = rnd32(seq[idx]); return; }
    idx -= n1;
    if (idx < n2) d_WcR[idx] = rnd32(Wc[idx]);
}

// side2 prep: W_attn, clf (padded), A_bl transpose, [Ws|Wo] pack
__global__ void prep_w2_kernel(const float* __restrict__ Wa,
                               const float* __restrict__ clf,
                               const float* __restrict__ A_bl,
                               const float* __restrict__ W_s,
                               const float* __restrict__ W_o)
{
    const long long n3 = (long long)WD * AD;
    const long long n4 = (long long)WD * NCP;
    const long long n5 = (long long)WD * PP;
    const long long n6 = (long long)WD * WD;
    long long idx = (long long)blockIdx.x * 256 + threadIdx.x;
    if (idx < n3) { d_WaR[idx] = rnd32(Wa[idx]); return; }
    idx -= n3;
    if (idx < n4) {
        int row = (int)(idx >> 7), col = (int)(idx & (NCP - 1));
        d_clfR[idx] = (col < NC) ? rnd32(clf[row * NC + col]) : 0.f;
        return;
    }
    idx -= n4;
    if (idx < n5) {
        int o = (int)(idx / PP), pq = (int)(idx % PP);
        d_Ablt[pq * WD + o] = rnd32(A_bl[idx]);
        return;
    }
    idx -= n5;
    if (idx < n6) {
        int k = (int)(idx / WD), j = (int)(idx % WD);
        d_Wso[(long long)k * (2 * WD) + j]      = rnd32(W_s[idx]);
        d_Wso[(long long)k * (2 * WD) + WD + j] = rnd32(W_o[idx]);
    }
}

__global__ void ga_kernel(const float* __restrict__ att, const int* __restrict__ ep)
{
    int b = blockIdx.z;
    int n = blockIdx.y / HEADS, h = blockIdx.y % HEADS;
    int s = blockIdx.x * blockDim.x + threadIdx.x;
    const float* ab = att + ((long long)(b * HEADS + h)) * SEQ * SEQ;
    float a = 0.f;
    #pragma unroll
    for (int m = 0; m < MENT; m++) {
        int e = ep[(b * NENT + n) * MENT + m];
        a += ab[(long long)e * SEQ + s];
    }
    d_ga[((long long)((b * NENT + n) * HEADS + h)) * SEQ + s] = a;
}

__global__ __launch_bounds__(256) void pa_tiled_kernel()
{
    extern __shared__ float sm[];          // [0:12288) gi, [12288:24576) gj
    __shared__ float sred[16 * 8];
    int b = blockIdx.z, ti = blockIdx.y, tj = blockIdx.x;
    int tid = threadIdx.x, lane = tid & 31, w = tid >> 5;

    float psum[16];
    #pragma unroll
    for (int p = 0; p < 16; p++) psum[p] = 0.f;

    for (int c = 0; c < 4; c++) {
        int s0 = c * 256;
        for (int l = tid; l < 3072; l += 256) {
            int il = l / 768;
            int rem = l - il * 768;
            int h = rem / 64, sq = rem - h * 64;
            int smoff = (il * 12 + h) * 256 + sq * 4;
            *(float4*)&sm[smoff] =
                *(const float4*)&d_ga[(((long long)(b * NENT + ti * 4 + il) * HEADS + h) << 10) + s0 + sq * 4];
            *(float4*)&sm[12288 + smoff] =
                *(const float4*)&d_ga[(((long long)(b * NENT + tj * 4 + il) * HEADS + h) << 10) + s0 + sq * 4];
        }
        __syncthreads();

        float acc[16];
        #pragma unroll
        for (int p = 0; p < 16; p++) acc[p] = 0.f;
        #pragma unroll
        for (int h = 0; h < HEADS; h++) {
            float ai[4], bj[4];
            #pragma unroll
            for (int il = 0; il < 4; il++) ai[il] = sm[(il * 12 + h) * 256 + tid];
            #pragma unroll
            for (int jl = 0; jl < 4; jl++) bj[jl] = sm[12288 + (jl * 12 + h) * 256 + tid];
            #pragma unroll
            for (int il = 0; il < 4; il++)
                #pragma unroll
                for (int jl = 0; jl < 4; jl++)
                    acc[il * 4 + jl] += ai[il] * bj[jl];
        }
        #pragma unroll
        for (int il = 0; il < 4; il++)
            #pragma unroll
            for (int jl = 0; jl < 4; jl++) {
                int p = il * 4 + jl;
                int ij = (ti * 4 + il) * NENT + tj * 4 + jl;
                d_pa[((long long)(b * NPAIR + ij) << 10) + s0 + tid] = rnd32(acc[p]);
                psum[p] += acc[p];
            }
        __syncthreads();
    }

    #pragma unroll
    for (int p = 0; p < 16; p++) {
        #pragma unroll
        for (int o = 16; o > 0; o >>= 1)
            psum[p] += __shfl_xor_sync(~0u, psum[p], o);
    }
    if (lane == 0)
        #pragma unroll
        for (int p = 0; p < 16; p++) sred[p * 8 + w] = psum[p];
    __syncthreads();
    if (tid < 16) {
        float s = 0.f;
        #pragma unroll
        for (int ww = 0; ww < 8; ww++) s += sred[tid * 8 + ww];
        int il = tid >> 2, jl = tid & 3;
        int ij = (ti * 4 + il) * NENT + tj * 4 + jl;
        d_painv[b * NPAIR + ij] = 1.0f / s;
    }
}

// one row per block; 160 threads (144 compute), float4 smem fills. Per-batch via rowOff.
__global__ __launch_bounds__(160) void P_kernel(int rowOff)
{
    __shared__ float zs[WD], zo[WD];
    long long row = rowOff + blockIdx.x;
    for (int w = threadIdx.x * 4; w < WD; w += 160 * 4) {
        *(float4*)&zs[w] = *(const float4*)&d_Zs[row * WD + w];
        *(float4*)&zo[w] = *(const float4*)&d_Zo[row * WD + w];
    }
    __syncthreads();
    int t = threadIdx.x;
    if (t < PP) {
        int p = t / DD, q = t % DD;
        float a = 0.f;
        #pragma unroll
        for (int k = 0; k < SPLITK; k++)
            a += zs[p * SPLITK + k] * zo[q * SPLITK + k];
        d_P[row * PP2 + t] = rnd32(a);   // cols 144..159 remain zero
    }
}

// e = tanh(sum of 3 t-partials) . v_attn  (t reduce folded in)
__global__ __launch_bounds__(256) void e_kernel(const float* __restrict__ v_attn)
{
    const long long plen = (long long)BATCH * NPAIR * AD;
    long long base = (long long)blockIdx.x * AD + threadIdx.x;
    int tid = threadIdx.x;
    float tv = d_part[base] + d_part[plen + base] + d_part[2 * plen + base];
    float val = tanhf(tv) * v_attn[tid];
    __shared__ float red[256];
    red[tid] = val;
    __syncthreads();
    for (int off = 128; off > 0; off >>= 1) {
        if (tid < off) red[tid] += red[tid + off];
        __syncthreads();
    }
    if (tid == 0) d_e[blockIdx.x] = red[0];
}

// row/col softmax (warp 0) + axis-attention residual folded through clf_W
__global__ __launch_bounds__(128) void rowcolC_kernel()
{
    __shared__ float srow[32], scol[32];
    int b = blockIdx.y, n = blockIdx.x;
    int tid = threadIdx.x;
    if (tid < 32) {
        int lane = tid;
        const float* eb = d_e + b * NPAIR;
        float v = eb[n * 32 + lane];
        float m = v;
        for (int o = 16; o > 0; o >>= 1) m = fmaxf(m, __shfl_xor_sync(~0u, m, o));
        float ex = expf(v - m);
        float s = ex;
        for (int o = 16; o > 0; o >>= 1) s += __shfl_xor_sync(~0u, s, o);
        srow[lane] = ex / s;
        float v2 = eb[lane * 32 + n];
        float m2 = v2;
        for (int o = 16; o > 0; o >>= 1) m2 = fmaxf(m2, __shfl_xor_sync(~0u, m2, o));
        float ex2 = expf(v2 - m2);
        float s2 = ex2;
        for (int o = 16; o > 0; o >>= 1) s2 += __shfl_xor_sync(~0u, s2, o);
        scol[lane] = ex2 / s2;
    }
    __syncthreads();
    int c = tid;
    if (c >= NC) return;
    const float* gc = d_gclf + (long long)b * NPAIR * NCP;
    float rs = 0.f, cs = 0.f;
    #pragma unroll 4
    for (int k = 0; k < NENT; k++) {
        rs += srow[k] * gc[(long long)(n * 32 + k) * NCP + c];
        cs += scol[k] * gc[(long long)(k * 32 + n) * NCP + c];
    }
    d_rgcg[(b * NENT + n) * NC + c] = rs;
    d_rgcg[(BATCH * NENT + b * NENT + n) * NC + c] = cs;
}

__global__ void final_kernel(const float* __restrict__ clf_b, float* __restrict__ out)
{
    long long idx = (long long)blockIdx.x * blockDim.x + threadIdx.x;
    const long long total = (long long)BATCH * NPAIR * NC;
    if (idx >= total) return;
    int c = (int)(idx % NC);
    long long rb = idx / NC;
    int ij = (int)(rb % NPAIR);
    int b = (int)(rb / NPAIR);
    int i = ij >> 5, j = ij & 31;
    out[idx] = d_gclf[rb * NCP + c]
             + d_rgcg[(b * NENT + i) * NC + c]
             + d_rgcg[(BATCH * NENT + b * NENT + j) * NC + c]
             + clf_b[c];
}

// ---------------- host launch ----------------
extern "C" void kernel_launch(void* const* d_in, const int* in_sizes, int n_in,
                              void* d_out, int out_size)
{
    const float* seq    = (const float*)d_in[0];
    const float* att    = (const float*)d_in[1];
    const int*   ep     = (const int*)  d_in[2];
    const float* W_s    = (const float*)d_in[3];
    const float* W_o    = (const float*)d_in[4];
    const float* W_c    = (const float*)d_in[5];
    const float* A_bl   = (const float*)d_in[6];
    const float* b_bl   = (const float*)d_in[7];
    const float* W_attn = (const float*)d_in[8];
    const float* v_attn = (const float*)d_in[9];
    const float* clf_W  = (const float*)d_in[10];
    const float* clf_b  = (const float*)d_in[11];
    float* out = (float*)d_out;

    float *p_rep, *p_rso, *p_Wso, *p_seqR, *p_WcR, *p_WaR, *p_clfR, *p_seqWc,
          *p_pa, *p_painv, *p_Zs, *p_Zo, *p_P, *p_Ablt, *p_g,
          *p_gclf, *p_part, *p_part2;
    cudaGetSymbolAddress((void**)&p_rep,   d_rep);
    cudaGetSymbolAddress((void**)&p_rso,   d_rso);
    cudaGetSymbolAddress((void**)&p_Wso,   d_Wso);
    cudaGetSymbolAddress((void**)&p_seqR,  d_seqR);
    cudaGetSymbolAddress((void**)&p_WcR,   d_WcR);
    cudaGetSymbolAddress((void**)&p_WaR,   d_WaR);
    cudaGetSymbolAddress((void**)&p_clfR,  d_clfR);
    cudaGetSymbolAddress((void**)&p_seqWc, d_seqWc);
    cudaGetSymbolAddress((void**)&p_pa,    d_pa);
    cudaGetSymbolAddress((void**)&p_painv, d_painv);
    cudaGetSymbolAddress((void**)&p_Zs,    d_Zs);
    cudaGetSymbolAddress((void**)&p_Zo,    d_Zo);
    cudaGetSymbolAddress((void**)&p_P,     d_P);
    cudaGetSymbolAddress((void**)&p_Ablt,  d_Ablt);
    cudaGetSymbolAddress((void**)&p_g,     d_g);
    cudaGetSymbolAddress((void**)&p_gclf,  d_gclf);
    cudaGetSymbolAddress((void**)&p_part,  d_part);
    cudaGetSymbolAddress((void**)&p_part2, d_part2);

    static cudaStream_t s1 = nullptr, s2 = nullptr;
    static cudaEvent_t evF, evJ1, evJ2, evF2, evJ3, evPG;
    static cudaEvent_t evZ[BATCH];
    static bool inited = false;
    if (!inited) {
        cudaFuncSetAttribute(pa_tiled_kernel,
                             cudaFuncAttributeMaxDynamicSharedMemorySize, 98304);
        cudaStreamCreateWithFlags(&s1, cudaStreamNonBlocking);
        cudaStreamCreateWithFlags(&s2, cudaStreamNonBlocking);
        cudaEventCreateWithFlags(&evF,  cudaEventDisableTiming);
        cudaEventCreateWithFlags(&evJ1, cudaEventDisableTiming);
        cudaEventCreateWithFlags(&evJ2, cudaEventDisableTiming);
        cudaEventCreateWithFlags(&evF2, cudaEventDisableTiming);
        cudaEventCreateWithFlags(&evJ3, cudaEventDisableTiming);
        cudaEventCreateWithFlags(&evPG, cudaEventDisableTiming);
        for (int b = 0; b < BATCH; b++)
            cudaEventCreateWithFlags(&evZ[b], cudaEventDisableTiming);
        inited = true;
    }

    // ---- fork: s1 = seqWc chain; s2 = weights/rep/rso; main = ga/pa ----
    cudaEventRecord(evF, 0);
    cudaStreamWaitEvent(s1, evF, 0);
    cudaStreamWaitEvent(s2, evF, 0);

    // s1: round seq+Wc, then seqWc = rnd(seqR @ WcR)  grid(12,8,4)=384
    {
        long long tot = (long long)BATCH * SEQ * HID + (long long)HID * WD;
        prep_seqWc_kernel<<<(unsigned)((tot + 255) / 256), 256, 0, s1>>>(seq, W_c);
        dim3 grid(WD / 64, SEQ / 128, BATCH);
        mma_gemm<0, 1><<<grid, 256, 0, s1>>>(p_seqR, p_WcR, p_seqWc, nullptr,
                                             SEQ, WD, HID,
                                             (long long)SEQ * HID, 0, (long long)SEQ * WD,
                                             1, 0, nullptr, 0.f, nullptr, 0, nullptr);
        cudaEventRecord(evJ1, s1);
    }
    // s2: remaining weight prep, rep, rso
    {
        long long totw = (long long)WD * AD + (long long)WD * NCP
                       + (long long)WD * PP + (long long)WD * WD;
        prep_w2_kernel<<<(unsigned)((totw + 255) / 256), 256, 0, s2>>>(
            W_attn, clf_W, A_bl, W_s, W_o);
        rep_kernel<<<BATCH * NENT, 256, 0, s2>>>(seq, ep);
        dim3 grid((2 * WD) / 64, 1, 6);
        mma_gemm<0, 0><<<grid, 256, 0, s2>>>(p_rep, p_Wso, p_part, nullptr,
                                             BATCH * NENT, 2 * WD, HID, 0, 0, 0,
                                             6, (long long)BATCH * NENT * 2 * WD,
                                             nullptr, 0.f, nullptr, 0, nullptr);
        reduce_add_kernel<<<(BATCH * NENT * 2 * WD + 255) / 256, 256, 0, s2>>>(
            p_part, p_rso, 6, (long long)BATCH * NENT * 2 * WD);
        cudaEventRecord(evJ2, s2);
    }
    // main: ga + pa
    {
        dim3 grid(SEQ / 256, NENT * HEADS, BATCH);
        ga_kernel<<<grid, 256>>>(att, ep);
    }
    {
        dim3 grid(8, 8, BATCH);
        pa_tiled_kernel<<<grid, 256, 98304>>>();
    }
    // join: fused GEMM needs seqWc (s1), rso (s2), pa/painv (main)
    cudaStreamWaitEvent(0, evJ1, 0);
    cudaStreamWaitEvent(0, evJ2, 0);

    // per-batch pipeline: main runs Zs_b; s2 runs P_b + g_b as each Zs_b lands.
    for (int b = 0; b < BATCH; b++) {
        dim3 grid(WD / 64, NPAIR / 128, 1);   // 96 blocks
        mma_gemm<3, 0><<<grid, 256>>>(
            p_pa + (long long)b * NPAIR * SEQ,
            p_seqWc + (long long)b * SEQ * WD,
            p_Zs + (long long)b * NPAIR * WD,
            p_Zo + (long long)b * NPAIR * WD,
            NPAIR, WD, SEQ, 0, 0, 0,
            1, 0,
            p_rso + (long long)b * NENT * 2 * WD, 0.f,
            p_rso + (long long)b * NENT * 2 * WD + WD, 2 * WD,
            p_painv + (long long)b * NPAIR);
        cudaEventRecord(evZ[b], 0);
        cudaStreamWaitEvent(s2, evZ[b], 0);
        P_kernel<<<NPAIR, 160, 0, s2>>>(b * NPAIR);
        dim3 ggrid(WD / 64, NPAIR / 128, 1);
        mma_gemm<0, 1><<<ggrid, 256, 0, s2>>>(
            p_P + (long long)b * NPAIR * PP2, p_Ablt,
            p_g + (long long)b * NPAIR * WD, nullptr,
            NPAIR, WD, PP2, 0, 0, 0,
            1, 0, b_bl, (float)SPLITK, nullptr, 0, nullptr);
    }
    cudaEventRecord(evPG, s2);
    cudaStreamWaitEvent(0, evPG, 0);

    // ---- fork 2: s1 = gclf; main = t -> e ----
    cudaEventRecord(evF2, 0);
    cudaStreamWaitEvent(s1, evF2, 0);
    {
        long long len = (long long)BATCH * NPAIR * NCP;
        dim3 grid(NCP / 64, (BATCH * NPAIR) / 128, 6);
        mma_gemm<0, 0><<<grid, 256, 0, s1>>>(p_g, p_clfR, p_part2, nullptr,
                                             BATCH * NPAIR, NCP, WD, 0, 0, 0,
                                             6, len, nullptr, 0.f, nullptr, 0, nullptr);
        reduce_add_kernel<<<(unsigned)((len + 255) / 256), 256, 0, s1>>>(
            p_part2, p_gclf, 6, len);
        cudaEventRecord(evJ3, s1);
    }
    // main: t partials = g @ WaR  split-K 3, grid(4,32,3)=384 (reduce folded into e)
    {
        long long len = (long long)BATCH * NPAIR * AD;
        dim3 grid(AD / 64, (BATCH * NPAIR) / 128, 3);
        mma_gemm<0, 0><<<grid, 256>>>(p_g, p_WaR, p_part, nullptr,
                                      BATCH * NPAIR, AD, WD, 0, 0, 0,
                                      3, len, nullptr, 0.f, nullptr, 0, nullptr);
    }
    e_kernel<<<BATCH * NPAIR, 256>>>(v_attn);
    cudaStreamWaitEvent(0, evJ3, 0);
    {
        dim3 grid(NENT, BATCH);
        rowcolC_kernel<<<grid, 128>>>();
    }
    {
        long long total = (long long)BATCH * NPAIR * NC;
        final_kernel<<<(unsigned)((total + 255) / 256), 256>>>(clf_b, out);
    }
}